// round 13
// baseline (speedup 1.0000x reference)
#include <cuda_runtime.h>
#include <cuda_bf16.h>
#include <cstdint>

#define BB  2
#define HH  16
#define SS  2048
#define DD  64
#define BHN (BB*HH)
#define TM  128
#define TN  128
#define NT  (SS/TN)
#define SCL 0.125f
#define PK  72     // bf16 smem pitch (144B rows -> conflict-free ldmatrix)

typedef unsigned long long ull;

// Per-row 1/sum(exp) (static device global, allocation-guard safe)
__device__ float g_invZ[BHN * SS];

// ---------------------------------------------------------------------------
__device__ __forceinline__ uint32_t s2u(const void* p) {
    uint32_t a;
    asm("{ .reg .u64 t; cvta.to.shared.u64 t, %1; cvt.u32.u64 %0, t; }" : "=r"(a) : "l"(p));
    return a;
}
__device__ __forceinline__ void cpa16(uint32_t saddr, const void* g) {
    asm volatile("cp.async.cg.shared.global [%0], [%1], 16;" :: "r"(saddr), "l"(g));
}
__device__ __forceinline__ void cpa_commit() { asm volatile("cp.async.commit_group;" ::: "memory"); }
__device__ __forceinline__ void cpa_wait0()  { asm volatile("cp.async.wait_group 0;" ::: "memory"); }

__device__ __forceinline__ void ldsm_x4(uint32_t r[4], uint32_t addr) {
    asm volatile("ldmatrix.sync.aligned.m8n8.x4.shared.b16 {%0,%1,%2,%3}, [%4];"
                 : "=r"(r[0]), "=r"(r[1]), "=r"(r[2]), "=r"(r[3]) : "r"(addr));
}
__device__ __forceinline__ void ldsm_x4t(uint32_t r[4], uint32_t addr) {
    asm volatile("ldmatrix.sync.aligned.m8n8.x4.trans.shared.b16 {%0,%1,%2,%3}, [%4];"
                 : "=r"(r[0]), "=r"(r[1]), "=r"(r[2]), "=r"(r[3]) : "r"(addr));
}
__device__ __forceinline__ void mma16816(float c[4], const uint32_t a[4], const uint32_t* b) {
    asm volatile(
        "mma.sync.aligned.m16n8k16.row.col.f32.bf16.bf16.f32 "
        "{%0,%1,%2,%3}, {%4,%5,%6,%7}, {%8,%9}, {%0,%1,%2,%3};"
        : "+f"(c[0]), "+f"(c[1]), "+f"(c[2]), "+f"(c[3])
        : "r"(a[0]), "r"(a[1]), "r"(a[2]), "r"(a[3]), "r"(b[0]), "r"(b[1]));
}

// fp32x4 -> bf16 hi/lo split, 4x u16 packed per ull
__device__ __forceinline__ void hilo4(float4 f, ull& hp, ull& lp) {
    __nv_bfloat16 h0 = __float2bfloat16(f.x), h1 = __float2bfloat16(f.y);
    __nv_bfloat16 h2 = __float2bfloat16(f.z), h3 = __float2bfloat16(f.w);
    __nv_bfloat16 l0 = __float2bfloat16(f.x - __bfloat162float(h0));
    __nv_bfloat16 l1 = __float2bfloat16(f.y - __bfloat162float(h1));
    __nv_bfloat16 l2 = __float2bfloat16(f.z - __bfloat162float(h2));
    __nv_bfloat16 l3 = __float2bfloat16(f.w - __bfloat162float(h3));
    hp = (ull)__bfloat16_as_ushort(h0) | ((ull)__bfloat16_as_ushort(h1) << 16)
       | ((ull)__bfloat16_as_ushort(h2) << 32) | ((ull)__bfloat16_as_ushort(h3) << 48);
    lp = (ull)__bfloat16_as_ushort(l0) | ((ull)__bfloat16_as_ushort(l1) << 16)
       | ((ull)__bfloat16_as_ushort(l2) << 32) | ((ull)__bfloat16_as_ushort(l3) << 48);
}
// fp32x2 -> hi/lo bf16x2 packed u32
__device__ __forceinline__ void hilo2(float x, float y, uint32_t& h, uint32_t& l) {
    __nv_bfloat16 hx = __float2bfloat16(x), hy = __float2bfloat16(y);
    __nv_bfloat16 lx = __float2bfloat16(x - __bfloat162float(hx));
    __nv_bfloat16 ly = __float2bfloat16(y - __bfloat162float(hy));
    h = (uint32_t)__bfloat16_as_ushort(hx) | ((uint32_t)__bfloat16_as_ushort(hy) << 16);
    l = (uint32_t)__bfloat16_as_ushort(lx) | ((uint32_t)__bfloat16_as_ushort(ly) << 16);
}

// ---------------------------------------------------------------------------
// Pass 1: e = exp(QK^T/8 + mask*-1e9) (unnormalized) -> wts; row sums -> g_invZ
// bf16 3-term split via mma.sync; K tile prefetched via cp.async stage.
// ---------------------------------------------------------------------------
#define O1_QHI 0
#define O1_QLO (O1_QHI + TM*PK*2)
#define O1_KHI (O1_QLO + TM*PK*2)
#define O1_KLO (O1_KHI + TM*PK*2)
#define O1_ST  (O1_KLO + TM*PK*2)       // raw fp32 K stage: 128x64x4 = 32 KB
#define SMEM1  (O1_ST + TM*DD*4)        // 106,496 B -> 2 CTAs/SM

__global__ void __launch_bounds__(256, 2)
qk_kernel(const float* __restrict__ q, const float* __restrict__ k,
          const float* __restrict__ mask, float* __restrict__ wts) {
    extern __shared__ __align__(16) char sm[];
    const uint32_t sb = s2u(sm);

    const int tid = threadIdx.x, w = tid >> 5, l = tid & 31;
    const int bh = blockIdx.x, qb = blockIdx.y, b = bh >> 4;   // HH=16

    const float* qp = q    + ((size_t)bh * SS + (size_t)qb * TM) * DD;
    const float* kp = k    + (size_t)bh * SS * DD;
    const float* mp = mask + ((size_t)b  * SS + (size_t)qb * TM) * SS;
    float*       wp = wts  + ((size_t)bh * SS + (size_t)qb * TM) * SS;

    // per-thread load mapping (shared by Q load / K stage fill / K convert)
    // lin = it*256+tid -> row = lin>>4, c4 = (lin&15)<<2
    // Q tile: load + split once (direct)
    #pragma unroll
    for (int it = 0; it < 8; it++) {
        int lin = it * 256 + tid, row = lin >> 4, c4 = (lin & 15) << 2;
        float4 f = *(const float4*)(qp + (size_t)row * DD + c4);
        ull hp, lp; hilo4(f, hp, lp);
        *(ull*)(sm + O1_QHI + row * (PK*2) + c4 * 2) = hp;
        *(ull*)(sm + O1_QLO + row * (PK*2) + c4 * 2) = lp;
    }
    // prologue: stage <- K(0)
    #pragma unroll
    for (int it = 0; it < 8; it++) {
        int lin = it * 256 + tid, row = lin >> 4, c4 = (lin & 15) << 2;
        cpa16(sb + O1_ST + row * 256 + c4 * 4, kp + (size_t)row * DD + c4);
    }
    cpa_commit();

    const int gq = l >> 2, qd = l & 3;
    const int row0 = w * 16 + gq, row1 = row0 + 8;
    const int a_r = l & 15, a_c = (l >> 4) * 8;
    const int b_r = l & 7, b_h = ((l >> 3) & 1) * 8, b_p = (l >> 4);

    float zrun0 = 0.f, zrun1 = 0.f;

    for (int t = 0; t < NT; t++) {
        __syncthreads();          // MMA readers of Khi/Klo (tile t-1) done
        cpa_wait0();              // stage holds K(t) (own bytes)
        // convert stage -> Khi/Klo (each thread reads exactly the bytes it filled)
        #pragma unroll
        for (int it = 0; it < 8; it++) {
            int lin = it * 256 + tid, row = lin >> 4, c4 = (lin & 15) << 2;
            float4 f = *(const float4*)(sm + O1_ST + row * 256 + c4 * 4);
            ull hp, lp; hilo4(f, hp, lp);
            *(ull*)(sm + O1_KHI + row * (PK*2) + c4 * 2) = hp;
            *(ull*)(sm + O1_KLO + row * (PK*2) + c4 * 2) = lp;
        }
        // issue stage <- K(t+1); in flight across MMA+epilogue
        {
            int tn = (t + 1 < NT) ? t + 1 : 0;
            #pragma unroll
            for (int it = 0; it < 8; it++) {
                int lin = it * 256 + tid, row = lin >> 4, c4 = (lin & 15) << 2;
                cpa16(sb + O1_ST + row * 256 + c4 * 4,
                      kp + (size_t)(tn * TN + row) * DD + c4);
            }
            cpa_commit();
        }
        __syncthreads();          // Khi/Klo visible to all

        float acc[16][4];
        #pragma unroll
        for (int i = 0; i < 16; i++)
            #pragma unroll
            for (int j = 0; j < 4; j++) acc[i][j] = 0.f;

        #pragma unroll
        for (int ks = 0; ks < 4; ks++) {
            uint32_t ah[4], al[4];
            uint32_t aaddr = sb + O1_QHI + ((w * 16 + a_r) * PK + ks * 16 + a_c) * 2;
            ldsm_x4(ah, aaddr);
            ldsm_x4(al, aaddr + (O1_QLO - O1_QHI));
            #pragma unroll
            for (int np = 0; np < 8; np++) {
                uint32_t bhr[4], blr[4];
                uint32_t baddr = sb + O1_KHI
                    + (((np * 2 + b_p) * 8 + b_r) * PK + ks * 16 + b_h) * 2;
                ldsm_x4(bhr, baddr);
                ldsm_x4(blr, baddr + (O1_KLO - O1_KHI));
                mma16816(acc[np*2+0], ah, bhr + 0);
                mma16816(acc[np*2+0], ah, blr + 0);
                mma16816(acc[np*2+0], al, bhr + 0);
                mma16816(acc[np*2+1], ah, bhr + 2);
                mma16816(acc[np*2+1], ah, blr + 2);
                mma16816(acc[np*2+1], al, bhr + 2);
            }
        }

        // Epilogue: mask + exp + store e, row sums
        float z0 = 0.f, z1 = 0.f;
        const float* m0p = mp + (size_t)row0 * SS + t * TN;
        const float* m1p = mp + (size_t)row1 * SS + t * TN;
        float* w0p = wp + (size_t)row0 * SS + t * TN;
        float* w1p = wp + (size_t)row1 * SS + t * TN;
        #pragma unroll
        for (int nt = 0; nt < 16; nt++) {
            int col = nt * 8 + qd * 2;
            float2 m0 = *(const float2*)(m0p + col);
            float2 m1 = *(const float2*)(m1p + col);
            float e00 = __expf(fmaf(m0.x, -1e9f, acc[nt][0] * SCL));
            float e01 = __expf(fmaf(m0.y, -1e9f, acc[nt][1] * SCL));
            float e10 = __expf(fmaf(m1.x, -1e9f, acc[nt][2] * SCL));
            float e11 = __expf(fmaf(m1.y, -1e9f, acc[nt][3] * SCL));
            *(float2*)(w0p + col) = make_float2(e00, e01);
            *(float2*)(w1p + col) = make_float2(e10, e11);
            z0 += e00 + e01;
            z1 += e10 + e11;
        }
        z0 += __shfl_xor_sync(0xffffffffu, z0, 1);
        z0 += __shfl_xor_sync(0xffffffffu, z0, 2);
        z1 += __shfl_xor_sync(0xffffffffu, z1, 1);
        z1 += __shfl_xor_sync(0xffffffffu, z1, 2);
        zrun0 += z0;
        zrun1 += z1;
    }

    if (qd == 0) {
        g_invZ[(size_t)bh * SS + (size_t)qb * TM + row0] = 1.0f / zrun0;
        g_invZ[(size_t)bh * SS + (size_t)qb * TM + row1] = 1.0f / zrun1;
    }
}

// ---------------------------------------------------------------------------
// Pass 2: normalize w in place; out = W @ V (bf16 3-term split).
// W loaded per-warp straight from gmem in MMA fragment order (no smem, no
// CTA-wide sync around the W phase); V via cp.async stage -> smem + ldsm.trans.
// ---------------------------------------------------------------------------
#define O2_VHI 0
#define O2_VLO (O2_VHI + TN*PK*2)
#define O2_VST (O2_VLO + TN*PK*2)       // raw fp32 V stage: 128x64x4 = 32 KB
#define SMEM2  (O2_VST + TN*DD*4)       // 69,632 B

__global__ void __launch_bounds__(256, 1)
pv_kernel(const float* __restrict__ v, float* __restrict__ wts,
          float* __restrict__ out) {
    extern __shared__ __align__(16) char sm[];
    const uint32_t sb = s2u(sm);

    const int tid = threadIdx.x, w = tid >> 5, l = tid & 31;
    const int bh = blockIdx.x, qb = blockIdx.y;

    const float* vp = v   + (size_t)bh * SS * DD;
    float*       wp = wts + ((size_t)bh * SS + (size_t)qb * TM) * SS;
    float*       op = out + ((size_t)bh * SS + (size_t)qb * TM) * DD;

    const int gq = l >> 2, qd = l & 3;
    const int row0 = w * 16 + gq, row1 = row0 + 8;
    const int v_r = l & 7, v_j = ((l >> 3) & 1) * 8, v_p = (l >> 4);

    // per-row normalizers live in registers (broadcast loads)
    const float iZ0 = g_invZ[(size_t)bh * SS + (size_t)qb * TM + row0];
    const float iZ1 = g_invZ[(size_t)bh * SS + (size_t)qb * TM + row1];

    // prologue: stage <- V(0)
    #pragma unroll
    for (int it = 0; it < 8; it++) {
        int lin = it * 256 + tid, j = lin >> 4, d4 = (lin & 15) << 2;
        cpa16(sb + O2_VST + j * 256 + d4 * 4, vp + (size_t)j * DD + d4);
    }
    cpa_commit();

    float acc[8][4];
    #pragma unroll
    for (int i = 0; i < 8; i++)
        #pragma unroll
        for (int j = 0; j < 4; j++) acc[i][j] = 0.f;

    for (int t = 0; t < NT; t++) {
        __syncthreads();          // Vhi/Vlo readers (tile t-1 MMAs) done
        cpa_wait0();              // stage holds V(t)
        #pragma unroll
        for (int it = 0; it < 8; it++) {
            int lin = it * 256 + tid, j = lin >> 4, d4 = (lin & 15) << 2;
            float4 f = *(const float4*)(sm + O2_VST + j * 256 + d4 * 4);
            ull hp, lp; hilo4(f, hp, lp);
            *(ull*)(sm + O2_VHI + j * (PK*2) + d4 * 2) = hp;
            *(ull*)(sm + O2_VLO + j * (PK*2) + d4 * 2) = lp;
        }
        {
            int tn = (t + 1 < NT) ? t + 1 : 0;
            #pragma unroll
            for (int it = 0; it < 8; it++) {
                int lin = it * 256 + tid, j = lin >> 4, d4 = (lin & 15) << 2;
                cpa16(sb + O2_VST + j * 256 + d4 * 4,
                      vp + (size_t)(tn * TN + j) * DD + d4);
            }
            cpa_commit();
        }
        __syncthreads();          // Vhi/Vlo ready

        // ---- per-warp W phase: gmem -> frags, normalize, store back ----
        float* w0p = wp + (size_t)row0 * SS + t * TN;
        float* w1p = wp + (size_t)row1 * SS + t * TN;
        uint32_t ah[8][4], al[8][4];
        #pragma unroll
        for (int nt = 0; nt < 16; nt++) {
            int col = nt * 8 + qd * 2;
            float2 e0 = *(const float2*)(w0p + col);
            float2 e1 = *(const float2*)(w1p + col);
            e0.x *= iZ0; e0.y *= iZ0;
            e1.x *= iZ1; e1.y *= iZ1;
            *(float2*)(w0p + col) = e0;
            *(float2*)(w1p + col) = e1;
            int c = nt >> 1, s = (nt & 1) << 1;   // chunk, frag slot (0 or 2)
            hilo2(e0.x, e0.y, ah[c][s + 0], al[c][s + 0]);
            hilo2(e1.x, e1.y, ah[c][s + 1], al[c][s + 1]);
        }

        // ---- PV MMAs ----
        #pragma unroll
        for (int c = 0; c < 8; c++) {
            #pragma unroll
            for (int np = 0; np < 4; np++) {
                uint32_t bhr[4], blr[4];
                uint32_t baddr = sb + O2_VHI
                    + ((c * 16 + v_j + v_r) * PK + (np * 2 + v_p) * 8) * 2;
                ldsm_x4t(bhr, baddr);
                ldsm_x4t(blr, baddr + (O2_VLO - O2_VHI));
                mma16816(acc[np*2+0], ah[c], bhr + 0);
                mma16816(acc[np*2+0], ah[c], blr + 0);
                mma16816(acc[np*2+0], al[c], bhr + 0);
                mma16816(acc[np*2+1], ah[c], bhr + 2);
                mma16816(acc[np*2+1], ah[c], blr + 2);
                mma16816(acc[np*2+1], al[c], bhr + 2);
            }
        }
    }

    // Epilogue: out[128][64]
    #pragma unroll
    for (int nt = 0; nt < 8; nt++) {
        int col = nt * 8 + qd * 2;
        *(float2*)(op + (size_t)row0 * DD + col) = make_float2(acc[nt][0], acc[nt][1]);
        *(float2*)(op + (size_t)row1 * DD + col) = make_float2(acc[nt][2], acc[nt][3]);
    }
}

// ---------------------------------------------------------------------------
extern "C" void kernel_launch(void* const* d_in, const int* in_sizes, int n_in,
                              void* d_out, int out_size) {
    (void)in_sizes; (void)n_in; (void)out_size;
    const float* q    = (const float*)d_in[0];
    const float* k    = (const float*)d_in[1];
    const float* v    = (const float*)d_in[2];
    const float* mask = (const float*)d_in[3];

    float* out = (float*)d_out;                        // [B,H,S,D]
    float* wts = out + (size_t)BB * HH * SS * DD;      // [B,H,S,S]

    cudaFuncSetAttribute(qk_kernel, cudaFuncAttributeMaxDynamicSharedMemorySize, SMEM1);
    cudaFuncSetAttribute(pv_kernel, cudaFuncAttributeMaxDynamicSharedMemorySize, SMEM2);

    dim3 grid(BHN, SS / TM);   // heads fastest -> per-batch mask slice stays L2-hot
    qk_kernel<<<grid, 256, SMEM1>>>(q, k, mask, wts);
    pv_kernel<<<grid, 256, SMEM2>>>(v, wts, out);
}